// round 12
// baseline (speedup 1.0000x reference)
#include <cuda_runtime.h>
#include <cstdint>

#define HH 512
#define WW 512
#define WORDS 16
#define SLAB 128
#define HALO 3
#define NTH 512
#define NWARPS 16
#define NOFF 12
#define SLABS (HH / SLAB)              // 4
#define MAXB 128
#define STRIP 8                        // rows per warp
#define CHROWS 2                       // rows per TMA chunk
#define CHBYTES (CHROWS * WW * 4)      // 4096 B
#define SLOTF (CHROWS * WW)            // 1024 floats per warp slot
#define BITS_WORDS ((SLAB + HALO) * WORDS + WORDS)   // 2112

// zero-initialized; every use paired with a reset -> deterministic graph replays
__device__ int g_cnt[MAXB * NOFF * 2];
__device__ unsigned g_arrive[MAXB];

__device__ __forceinline__ void mbar_init(unsigned a, unsigned cnt) {
    asm volatile("mbarrier.init.shared.b64 [%0], %1;" :: "r"(a), "r"(cnt) : "memory");
}
__device__ __forceinline__ void mbar_expect_tx(unsigned a, unsigned bytes) {
    asm volatile("mbarrier.arrive.expect_tx.shared.b64 _, [%0], %1;"
                 :: "r"(a), "r"(bytes) : "memory");
}
__device__ __forceinline__ void bulk_g2s(unsigned dst, const float* src,
                                         unsigned bytes, unsigned mbar) {
    asm volatile("cp.async.bulk.shared::cluster.global.mbarrier::complete_tx::bytes "
                 "[%0], [%1], %2, [%3];"
                 :: "r"(dst), "l"(src), "r"(bytes), "r"(mbar) : "memory");
}
__device__ __forceinline__ void mbar_wait(unsigned a, unsigned parity) {
    asm volatile(
        "{\n\t"
        ".reg .pred P1;\n\t"
        "WAIT_LOOP_%=:\n\t"
        "mbarrier.try_wait.parity.shared.b64 P1, [%0], %1;\n\t"
        "@P1 bra.uni WAIT_DONE_%=;\n\t"
        "bra.uni WAIT_LOOP_%=;\n\t"
        "WAIT_DONE_%=:\n\t"
        "}"
        :: "r"(a), "r"(parity) : "memory");
}

// evaluate all 12 offsets for bit-word (r, w)
__device__ __forceinline__ void eval12(const unsigned* __restrict__ bits,
                                       int r, int w,
                                       const int* __restrict__ rl,
                                       unsigned* __restrict__ acc)
{
    constexpr int RS[NOFF] = {0, 1, 1, 1, 0, 2, 2, 2, 0, 3, 3, 3};
    constexpr int CS[NOFF] = {1, 1, 0, -1, 2, 2, 0, -2, 3, 3, 0, -3};
    const bool firstw = (w == 0);
    const bool lastw  = (w == WORDS - 1);
    const int i = r * WORDS + w;
    const unsigned A = bits[i];

    #pragma unroll
    for (int o = 0; o < NOFF; ++o) {
        const int R = RS[o];
        const int C = CS[o];
        const int bi = i + R * WORDS;
        unsigned B;
        if (C > 0)       B = __funnelshift_r(bits[bi], bits[bi + 1], C);
        else if (C < 0)  B = __funnelshift_l(bits[bi - 1], bits[bi], -C);
        else             B = bits[bi];

        unsigned m = 0xffffffffu;
        if (C > 0 && lastw)  m = 0xffffffffu >> C;
        if (C < 0 && firstw) m = 0xffffffffu << (-C);
        if (r >= rl[R]) m = 0u;              // last-slab row clip

        acc[o] += (unsigned)(__popc((A ^ B) & m) << 16)
                |  (unsigned)__popc((A & B) & m);
    }
}

extern __shared__ unsigned char dynsmem[];

__global__ __launch_bounds__(NTH, 3)
void glcm_wtma(const float* __restrict__ in, float* __restrict__ out)
{
    constexpr int RS[NOFF] = {0, 1, 1, 1, 0, 2, 2, 2, 0, 3, 3, 3};
    constexpr int CS[NOFF] = {1, 1, 0, -1, 2, 2, 0, -2, 3, 3, 0, -3};

    float*    sbuf = reinterpret_cast<float*>(dynsmem);               // 16 x 4KB
    unsigned* bits = reinterpret_cast<unsigned*>(dynsmem + NWARPS * CHBYTES);
    __shared__ unsigned long long s_mbar[NWARPS];
    __shared__ int s_diff[NOFF];
    __shared__ int s_n11[NOFF];
    __shared__ int s_last;

    const int tid  = threadIdx.x;
    const int lane = tid & 31;
    const int warp = tid >> 5;
    const int r0   = blockIdx.x * SLAB;
    const int b    = blockIdx.y;
    const float* img = in + ((size_t)b * HH + r0) * WW;

    if (tid < NOFF) { s_diff[tid] = 0; s_n11[tid] = 0; }

    int rl[4];
    #pragma unroll
    for (int R = 0; R < 4; ++R) rl[R] = min(SLAB, HH - R - r0);

    // ---- per-warp TMA strip streaming (no block barriers) -------------------
    const unsigned mb = (unsigned)__cvta_generic_to_shared(&s_mbar[warp]);
    if (lane == 0) mbar_init(mb, 1u);
    __syncwarp();

    const int strip = warp * STRIP;
    const bool haloed = (warp == NWARPS - 1) && (r0 + SLAB < HH);
    const int nch = 4 + (haloed ? 2 : 0);      // chunks 4: rows 128-129, 5: row 130

    float* slot = sbuf + warp * SLOTF;
    const unsigned slot_s = (unsigned)__cvta_generic_to_shared(slot);

    // chunk k -> first row, byte count
    #define CH_ROW(k)   ((k) < 4 ? strip + 2 * (k) : SLAB + 2 * ((k) - 4))
    #define CH_BYTES(k) ((k) == 5 ? (unsigned)(WW * 4) : (unsigned)CHBYTES)

    if (lane == 0) {                           // prime chunk 0
        mbar_expect_tx(mb, CH_BYTES(0));
        bulk_g2s(slot_s, img + CH_ROW(0) * WW, CH_BYTES(0), mb);
    }

    unsigned acc[NOFF];
    #pragma unroll
    for (int o = 0; o < NOFF; ++o) acc[o] = 0;

    int from = strip;                          // next own a-row to count
    for (int k = 0; k < nch; ++k) {
        mbar_wait(mb, (unsigned)(k & 1));

        // pack chunk k: rows CH_ROW(k) .. (+nr)
        const int gr = CH_ROW(k);
        const int nr = (CH_BYTES(k) == CHBYTES) ? 2 : 1;
        for (int j = 0; j < nr; ++j) {
            const float* rp = slot + j * WW;
            unsigned b4[4];
            #pragma unroll
            for (int w = 0; w < WORDS; ++w) {
                float v = rp[w * 32 + lane];
                b4[w & 3] = __ballot_sync(0xffffffffu, v > 0.0f);
                if ((w & 3) == 3 && lane == 0)
                    *reinterpret_cast<uint4*>(&bits[(gr + j) * WORDS + (w - 3)])
                        = make_uint4(b4[0], b4[1], b4[2], b4[3]);
            }
        }
        __syncwarp();                          // lane0 STS visible warp-wide

        // reissue next chunk into the same slot (pack done -> slot free)
        if (lane == 0 && k + 1 < nch) {
            mbar_expect_tx(mb, CH_BYTES(k + 1));
            bulk_g2s(slot_s, img + CH_ROW(k + 1) * WW, CH_BYTES(k + 1), mb);
        }

        // count own a-rows whose +3 dependency just landed (overlap TMA flight)
        int hi = strip + 2 * k - 1;            // a-row r needs rows <= r+3
        if (hi > strip + 5) hi = strip + 5;
        if (hi > from) {
            const int cnt = (hi - from) * WORDS;
            for (int e = lane; e < cnt; e += 32)
                eval12(bits, from + (e >> 4), e & 15, rl, acc);
            from = hi;
        }
    }
    // remaining self-contained own rows (up to strip+5 exclusive)
    {
        const int hi = strip + 5;
        const int cnt = (hi - from) * WORDS;
        for (int e = lane; e < cnt; e += 32)
            eval12(bits, from + (e >> 4), e & 15, rl, acc);
    }

    __syncthreads();                           // the ONLY block barrier

    // ---- deferred boundary rows: r % 8 in {5,6,7}, all strips ---------------
    for (int idx = tid; idx < NWARPS * 3 * WORDS; idx += NTH) {
        const int dr = idx >> 4;               // 0..47
        const int q  = dr / 3;
        const int rr = dr - 3 * q;
        eval12(bits, STRIP * q + 5 + rr, idx & 15, rl, acc);
    }

    // ---- reduce: warp -> block -> global -------------------------------------
    #pragma unroll
    for (int o = 0; o < NOFF; ++o) {
        unsigned v = __reduce_add_sync(0xffffffffu, acc[o]);
        if (lane == 0) {
            atomicAdd(&s_diff[o], (int)(v >> 16));
            atomicAdd(&s_n11[o],  (int)(v & 0xffffu));
        }
    }
    __syncthreads();

    if (tid < NOFF) {
        atomicAdd(&g_cnt[(b * NOFF + tid) * 2 + 0], s_diff[tid]);
        atomicAdd(&g_cnt[(b * NOFF + tid) * 2 + 1], s_n11[tid]);
    }

    // ---- last slab-block of this image finalizes -----------------------------
    if (tid == 0) {
        __threadfence();
        unsigned t = atomicAdd(&g_arrive[b], 1u);
        s_last = (t == SLABS - 1);
    }
    __syncthreads();

    if (s_last && tid < NOFF) {
        const int idx  = b * NOFF + tid;
        const int diff = atomicExch(&g_cnt[idx * 2 + 0], 0);   // read + reset
        const int n11  = atomicExch(&g_cnt[idx * 2 + 1], 0);
        if (tid == 0) atomicExch(&g_arrive[b], 0u);

        const int R  = RS[tid];
        const int Ca = CS[tid] < 0 ? -CS[tid] : CS[tid];
        const int N  = (HH - R) * (WW - Ca);
        const int n00 = N - n11 - diff;

        const float inv = 1.0f / (float)(2 * N - 4 * n00);
        float* o = out + (size_t)b * (NOFF * 4) + tid * 4;
        o[0] = (float)(4 * n00) * inv;
        const float v1 = (float)(2 * diff - 4 * n00) * inv;
        o[1] = v1;
        o[2] = v1;
        o[3] = (float)(2 * (N - 2 * diff)) * inv;
    }
}

extern "C" void kernel_launch(void* const* d_in, const int* in_sizes, int n_in,
                              void* d_out, int out_size)
{
    (void)n_in; (void)out_size;
    const int batch = in_sizes[0] / (HH * WW);           // 128
    const int smem = NWARPS * CHBYTES + BITS_WORDS * 4;  // 65536 + 8448 = 73984
    cudaFuncSetAttribute(glcm_wtma, cudaFuncAttributeMaxDynamicSharedMemorySize, smem);
    dim3 grid(SLABS, batch);                             // 4 x 128 = 512 blocks
    glcm_wtma<<<grid, NTH, smem>>>((const float*)d_in[0], (float*)d_out);
}

// round 13
// speedup vs baseline: 1.1168x; 1.1168x over previous
#include <cuda_runtime.h>
#include <cstdint>

#define HH 512
#define WW 512
#define WORDS 16
#define SLAB 128
#define HALO 3
#define NTH 512
#define NWARPS 16
#define NOFF 12
#define SLABS (HH / SLAB)
#define MAXB 128
#define BITS_WORDS ((SLAB + HALO) * WORDS + WORDS)   // 2112 incl. guard

// zero-initialized; every use paired with a reset -> deterministic graph replays
__device__ int g_cnt[MAXB * NOFF * 2];     // [image][offset]{diff, n11}
__device__ unsigned g_arrive[MAXB];

// evaluate all 12 offsets for bit-word (r, w)
__device__ __forceinline__ void eval12(const unsigned* __restrict__ bits,
                                       int r, int w,
                                       const int* __restrict__ rl,
                                       unsigned* __restrict__ acc)
{
    constexpr int RS[NOFF] = {0, 1, 1, 1, 0, 2, 2, 2, 0, 3, 3, 3};
    constexpr int CS[NOFF] = {1, 1, 0, -1, 2, 2, 0, -2, 3, 3, 0, -3};
    const bool firstw = (w == 0);
    const bool lastw  = (w == WORDS - 1);
    const int i = r * WORDS + w;
    const unsigned A = bits[i];

    #pragma unroll
    for (int o = 0; o < NOFF; ++o) {
        const int R = RS[o];
        const int C = CS[o];
        const int bi = i + R * WORDS;
        unsigned B;
        if (C > 0)       B = __funnelshift_r(bits[bi], bits[bi + 1], C);
        else if (C < 0)  B = __funnelshift_l(bits[bi - 1], bits[bi], -C);
        else             B = bits[bi];

        unsigned m = 0xffffffffu;
        if (C > 0 && lastw)  m = 0xffffffffu >> C;
        if (C < 0 && firstw) m = 0xffffffffu << (-C);
        if (r >= rl[R]) m = 0u;              // last-slab row clip

        acc[o] += (unsigned)(__popc((A ^ B) & m) << 16)
                |  (unsigned)__popc((A & B) & m);
    }
}

// pack one 512-col row into 16 bit-words via float4 + nibble + shfl OR-tree.
// Lane layout: chunk c (128 cols), lane l covers cols c*128 + 4l .. +3.
// Word g (32 cols) of chunk c is OR-reduced over lanes 8g..8g+7.
__device__ __forceinline__ void pack_row(const float* __restrict__ rowp,
                                         unsigned* __restrict__ dst,
                                         int lane)
{
    const float4* rp4 = reinterpret_cast<const float4*>(rowp);
    float4 v[4];
    #pragma unroll
    for (int c = 0; c < 4; ++c) v[c] = rp4[c * 32 + lane];   // 4 LDG.128 hoisted

    unsigned pk[4];
    const int sh = (lane & 7) * 4;
    #pragma unroll
    for (int c = 0; c < 4; ++c) {
        unsigned nib = (v[c].x > 0.0f ? 1u : 0u)
                     | (v[c].y > 0.0f ? 2u : 0u)
                     | (v[c].z > 0.0f ? 4u : 0u)
                     | (v[c].w > 0.0f ? 8u : 0u);
        unsigned p = nib << sh;
        p |= __shfl_xor_sync(0xffffffffu, p, 1);
        p |= __shfl_xor_sync(0xffffffffu, p, 2);
        p |= __shfl_xor_sync(0xffffffffu, p, 4);
        pk[c] = p;
    }
    if ((lane & 7) == 0) {
        const int g = lane >> 3;
        #pragma unroll
        for (int c = 0; c < 4; ++c) dst[c * 4 + g] = pk[c];
    }
}

__global__ __launch_bounds__(NTH, 3)
void glcm_v4(const float* __restrict__ in, float* __restrict__ out)
{
    constexpr int RS[NOFF] = {0, 1, 1, 1, 0, 2, 2, 2, 0, 3, 3, 3};
    constexpr int CS[NOFF] = {1, 1, 0, -1, 2, 2, 0, -2, 3, 3, 0, -3};

    __shared__ unsigned bits[BITS_WORDS];
    __shared__ int s_diff[NOFF];
    __shared__ int s_n11[NOFF];
    __shared__ int s_last;

    const int tid  = threadIdx.x;
    const int lane = tid & 31;
    const int warp = tid >> 5;
    const int r0   = blockIdx.x * SLAB;
    const int b    = blockIdx.y;
    const float* img = in + ((size_t)b * HH + r0) * WW;

    if (tid < NOFF) { s_diff[tid] = 0; s_n11[tid] = 0; }
    if (tid == 0) bits[(SLAB + HALO) * WORDS] = 0u;   // guard word

    int rl[4];
    #pragma unroll
    for (int R = 0; R < 4; ++R) rl[R] = min(SLAB, HH - R - r0);

    // ---- pack own 8-row band (float4 loads, shfl OR-tree; no barriers) ------
    const int base = warp * 8;
    #pragma unroll
    for (int j = 0; j < 8; ++j)
        pack_row(img + (base + j) * WW, &bits[(base + j) * WORDS], lane);

    // warps 0..2 pack the cross-slab halo rows (skipped for last slab)
    if (warp < HALO && r0 + SLAB < HH)
        pack_row(img + (SLAB + warp) * WW, &bits[(SLAB + warp) * WORDS], lane);

    __syncwarp();    // order group-leader STS before LDS, warp scope

    // ---- own-band count: a-rows base..base+4 (self-contained, no sync) ------
    unsigned acc[NOFF];
    #pragma unroll
    for (int o = 0; o < NOFF; ++o) acc[o] = 0;

    for (int e = lane; e < 5 * WORDS; e += 32)
        eval12(bits, base + (e >> 4), e & 15, rl, acc);

    __syncthreads();   // the ONLY block barrier in the hot path

    // ---- deferred boundary rows: r % 8 in {5,6,7}, all bands ----------------
    for (int idx = tid; idx < NWARPS * 3 * WORDS; idx += NTH) {
        const int dr = idx >> 4;            // 0..47
        const int q  = dr / 3;
        const int rr = dr - 3 * q;
        eval12(bits, 8 * q + 5 + rr, idx & 15, rl, acc);
    }

    // ---- reduce: warp -> block -> global -------------------------------------
    #pragma unroll
    for (int o = 0; o < NOFF; ++o) {
        unsigned v = __reduce_add_sync(0xffffffffu, acc[o]);
        if (lane == 0) {
            atomicAdd(&s_diff[o], (int)(v >> 16));
            atomicAdd(&s_n11[o],  (int)(v & 0xffffu));
        }
    }
    __syncthreads();

    if (tid < NOFF) {
        atomicAdd(&g_cnt[(b * NOFF + tid) * 2 + 0], s_diff[tid]);
        atomicAdd(&g_cnt[(b * NOFF + tid) * 2 + 1], s_n11[tid]);
    }

    // ---- last slab-block of this image finalizes -----------------------------
    if (tid == 0) {
        __threadfence();
        unsigned t = atomicAdd(&g_arrive[b], 1u);
        s_last = (t == SLABS - 1);
    }
    __syncthreads();

    if (s_last && tid < NOFF) {
        const int idx  = b * NOFF + tid;
        const int diff = atomicExch(&g_cnt[idx * 2 + 0], 0);   // read + reset
        const int n11  = atomicExch(&g_cnt[idx * 2 + 1], 0);
        if (tid == 0) atomicExch(&g_arrive[b], 0u);

        const int R  = RS[tid];
        const int Ca = CS[tid] < 0 ? -CS[tid] : CS[tid];
        const int N  = (HH - R) * (WW - Ca);
        const int n00 = N - n11 - diff;

        const float inv = 1.0f / (float)(2 * N - 4 * n00);
        float* o = out + (size_t)b * (NOFF * 4) + tid * 4;
        o[0] = (float)(4 * n00) * inv;
        const float v1 = (float)(2 * diff - 4 * n00) * inv;
        o[1] = v1;
        o[2] = v1;
        o[3] = (float)(2 * (N - 2 * diff)) * inv;
    }
}

extern "C" void kernel_launch(void* const* d_in, const int* in_sizes, int n_in,
                              void* d_out, int out_size)
{
    (void)n_in; (void)out_size;
    const int batch = in_sizes[0] / (HH * WW);    // 128
    dim3 grid(SLABS, batch);                      // 4 x 128 = 512 blocks
    glcm_v4<<<grid, NTH>>>((const float*)d_in[0], (float*)d_out);
}